// round 3
// baseline (speedup 1.0000x reference)
#include <cuda_runtime.h>

#define MAXN 65536
#define MAXE 1048576
#define D 128
#define C 64

// -------- scratch (static device globals; no allocation) --------
__device__ __align__(16) float g_a1[(size_t)MAXN * D];
__device__ __align__(16) float g_h [(size_t)MAXN * D];
__device__ __align__(16) float g_a2[(size_t)MAXN * D];
__device__ __align__(16) float g_logits[(size_t)MAXN * C];
__device__ int   g_counts[MAXN];
__device__ int   g_offsets[MAXN];
__device__ int   g_scan[MAXN];
__device__ int   g_cursor[MAXN];
__device__ int   g_src_sorted[MAXE];
__device__ int   g_bsum[512];
__device__ float g_acc[2];   // {nll_sum, mask_sum}

// -------- init --------
__global__ void k_init(int n) {
    int i = blockIdx.x * blockDim.x + threadIdx.x;
    if (i < n) { g_counts[i] = 0; g_cursor[i] = 0; }
    if (i == 0) { g_acc[0] = 0.f; g_acc[1] = 0.f; }
}

// -------- CSR build --------
__global__ void k_hist(const int* __restrict__ dst, int e) {
    int i = blockIdx.x * blockDim.x + threadIdx.x;
    if (i < e) atomicAdd(&g_counts[dst[i]], 1);
}

__global__ void k_scan1(int n) {
    __shared__ int sm[512];
    int i = blockIdx.x * 512 + threadIdx.x;
    int v = (i < n) ? g_counts[i] : 0;
    sm[threadIdx.x] = v; __syncthreads();
    for (int off = 1; off < 512; off <<= 1) {
        int t = (threadIdx.x >= off) ? sm[threadIdx.x - off] : 0;
        __syncthreads();
        sm[threadIdx.x] += t;
        __syncthreads();
    }
    if (i < n) g_scan[i] = sm[threadIdx.x];
    if (threadIdx.x == 511) g_bsum[blockIdx.x] = sm[511];
}

__global__ void k_scan2(int nb) {
    __shared__ int sm[512];
    int i = threadIdx.x;
    int v = (i < nb) ? g_bsum[i] : 0;
    sm[i] = v; __syncthreads();
    for (int off = 1; off < 512; off <<= 1) {
        int t = (i >= off) ? sm[i - off] : 0;
        __syncthreads();
        sm[i] += t;
        __syncthreads();
    }
    if (i < nb) g_bsum[i] = sm[i] - v;   // exclusive prefix of block sums
}

__global__ void k_scan3(int n) {
    int i = blockIdx.x * blockDim.x + threadIdx.x;
    if (i < n) g_offsets[i] = g_scan[i] - g_counts[i] + g_bsum[i >> 9];
}

__global__ void k_scatter(const int* __restrict__ src, const int* __restrict__ dst, int e) {
    int i = blockIdx.x * blockDim.x + threadIdx.x;
    if (i < e) {
        int d = dst[i];
        int p = g_offsets[d] + atomicAdd(&g_cursor[d], 1);
        g_src_sorted[p] = src[i];
    }
}

// -------- mean aggregation: one warp per node --------
__global__ void __launch_bounds__(256) k_aggr(const float* __restrict__ in,
                                              float* __restrict__ out, int n) {
    int w    = (blockIdx.x * blockDim.x + threadIdx.x) >> 5;
    int lane = threadIdx.x & 31;
    if (w >= n) return;
    int start = g_offsets[w];
    int cnt   = g_counts[w];
    const float4* b = (const float4*)in;
    float4 acc = make_float4(0.f, 0.f, 0.f, 0.f);
    int i = 0;
    for (; i + 1 < cnt; i += 2) {
        int s0 = g_src_sorted[start + i];
        int s1 = g_src_sorted[start + i + 1];
        float4 v0 = b[(size_t)s0 * 32 + lane];
        float4 v1 = b[(size_t)s1 * 32 + lane];
        acc.x += v0.x + v1.x; acc.y += v0.y + v1.y;
        acc.z += v0.z + v1.z; acc.w += v0.w + v1.w;
    }
    if (i < cnt) {
        int s = g_src_sorted[start + i];
        float4 v = b[(size_t)s * 32 + lane];
        acc.x += v.x; acc.y += v.y; acc.z += v.z; acc.w += v.w;
    }
    float inv = 1.0f / fmaxf((float)cnt, 1.0f);
    ((float4*)out)[(size_t)w * 32 + lane] =
        make_float4(acc.x * inv, acc.y * inv, acc.z * inv, acc.w * inv);
}

// -------- layer 1: h = relu(A @ W1l + X @ W1r + b1), D->D --------
__global__ void __launch_bounds__(256) k_dense1(const float* __restrict__ A,
                                                const float* __restrict__ X,
                                                const float* __restrict__ Wl,
                                                const float* __restrict__ Wr,
                                                const float* __restrict__ bias,
                                                float* __restrict__ out, int n) {
    extern __shared__ float sm[];
    float* sWl = sm;            // 128*128
    float* sWr = sm + 16384;    // 128*128
    float* sA  = sm + 32768;    // 64*128
    float* sX  = sm + 40960;    // 64*128

    for (int i = threadIdx.x; i < 4096; i += 256) {
        ((float4*)sWl)[i] = ((const float4*)Wl)[i];
        ((float4*)sWr)[i] = ((const float4*)Wr)[i];
    }
    int node0 = blockIdx.x * 64;
    for (int i = threadIdx.x; i < 2048; i += 256) {
        int r = i >> 5, c = i & 31;
        int node = node0 + r;
        float4 va = make_float4(0.f, 0.f, 0.f, 0.f), vx = va;
        if (node < n) {
            va = ((const float4*)A)[(size_t)node * 32 + c];
            vx = ((const float4*)X)[(size_t)node * 32 + c];
        }
        ((float4*)sA)[i] = va;
        ((float4*)sX)[i] = vx;
    }
    __syncthreads();

    int ty = threadIdx.x >> 4, tx = threadIdx.x & 15;
    int m0 = ty * 4, j0 = tx * 8;
    float acc[4][8];
#pragma unroll
    for (int a = 0; a < 4; a++)
#pragma unroll
        for (int b = 0; b < 8; b++) acc[a][b] = 0.f;

#pragma unroll 4
    for (int k = 0; k < 128; k++) {
        float4 wl0 = *(float4*)(sWl + k * 128 + j0);
        float4 wl1 = *(float4*)(sWl + k * 128 + j0 + 4);
        float4 wr0 = *(float4*)(sWr + k * 128 + j0);
        float4 wr1 = *(float4*)(sWr + k * 128 + j0 + 4);
#pragma unroll
        for (int mi = 0; mi < 4; mi++) {
            float a = sA[(m0 + mi) * 128 + k];
            float x = sX[(m0 + mi) * 128 + k];
            acc[mi][0] += a * wl0.x + x * wr0.x;
            acc[mi][1] += a * wl0.y + x * wr0.y;
            acc[mi][2] += a * wl0.z + x * wr0.z;
            acc[mi][3] += a * wl0.w + x * wr0.w;
            acc[mi][4] += a * wl1.x + x * wr1.x;
            acc[mi][5] += a * wl1.y + x * wr1.y;
            acc[mi][6] += a * wl1.z + x * wr1.z;
            acc[mi][7] += a * wl1.w + x * wr1.w;
        }
    }

    float4 b0 = *(const float4*)(bias + j0);
    float4 b1v = *(const float4*)(bias + j0 + 4);
#pragma unroll
    for (int mi = 0; mi < 4; mi++) {
        int node = node0 + m0 + mi;
        if (node < n) {
            float4 o0 = make_float4(fmaxf(acc[mi][0] + b0.x, 0.f),
                                    fmaxf(acc[mi][1] + b0.y, 0.f),
                                    fmaxf(acc[mi][2] + b0.z, 0.f),
                                    fmaxf(acc[mi][3] + b0.w, 0.f));
            float4 o1 = make_float4(fmaxf(acc[mi][4] + b1v.x, 0.f),
                                    fmaxf(acc[mi][5] + b1v.y, 0.f),
                                    fmaxf(acc[mi][6] + b1v.z, 0.f),
                                    fmaxf(acc[mi][7] + b1v.w, 0.f));
            *(float4*)(out + (size_t)node * 128 + j0)     = o0;
            *(float4*)(out + (size_t)node * 128 + j0 + 4) = o1;
        }
    }
}

// -------- layer 2: logits = A @ W2l + H @ W2r + b2, D->C --------
__global__ void __launch_bounds__(256) k_dense2(const float* __restrict__ A,
                                                const float* __restrict__ H,
                                                const float* __restrict__ Wl,
                                                const float* __restrict__ Wr,
                                                const float* __restrict__ bias,
                                                float* __restrict__ out, int n) {
    extern __shared__ float sm[];
    float* sWl = sm;            // 128*64
    float* sWr = sm + 8192;     // 128*64
    float* sA  = sm + 16384;    // 64*128
    float* sX  = sm + 24576;    // 64*128

    for (int i = threadIdx.x; i < 2048; i += 256) {
        ((float4*)sWl)[i] = ((const float4*)Wl)[i];
        ((float4*)sWr)[i] = ((const float4*)Wr)[i];
    }
    int node0 = blockIdx.x * 64;
    for (int i = threadIdx.x; i < 2048; i += 256) {
        int r = i >> 5, c = i & 31;
        int node = node0 + r;
        float4 va = make_float4(0.f, 0.f, 0.f, 0.f), vx = va;
        if (node < n) {
            va = ((const float4*)A)[(size_t)node * 32 + c];
            vx = ((const float4*)H)[(size_t)node * 32 + c];
        }
        ((float4*)sA)[i] = va;
        ((float4*)sX)[i] = vx;
    }
    __syncthreads();

    int ty = threadIdx.x >> 4, tx = threadIdx.x & 15;
    int m0 = ty * 4, j0 = tx * 4;
    float acc[4][4];
#pragma unroll
    for (int a = 0; a < 4; a++)
#pragma unroll
        for (int b = 0; b < 4; b++) acc[a][b] = 0.f;

#pragma unroll 4
    for (int k = 0; k < 128; k++) {
        float4 wl = *(float4*)(sWl + k * 64 + j0);
        float4 wr = *(float4*)(sWr + k * 64 + j0);
#pragma unroll
        for (int mi = 0; mi < 4; mi++) {
            float a = sA[(m0 + mi) * 128 + k];
            float x = sX[(m0 + mi) * 128 + k];
            acc[mi][0] += a * wl.x + x * wr.x;
            acc[mi][1] += a * wl.y + x * wr.y;
            acc[mi][2] += a * wl.z + x * wr.z;
            acc[mi][3] += a * wl.w + x * wr.w;
        }
    }

    float4 bb = *(const float4*)(bias + j0);
#pragma unroll
    for (int mi = 0; mi < 4; mi++) {
        int node = node0 + m0 + mi;
        if (node < n) {
            float4 o = make_float4(acc[mi][0] + bb.x, acc[mi][1] + bb.y,
                                   acc[mi][2] + bb.z, acc[mi][3] + bb.w);
            *(float4*)(out + (size_t)node * 64 + j0) = o;
        }
    }
}

// -------- loss: warp-per-node logsumexp + masked NLL reduction --------
// mask is read as 32-bit words: nonzero test is correct for BOTH int32 (1)
// and float32 (0x3f800000) encodings of a JAX bool mask.
__global__ void __launch_bounds__(1024) k_loss(const int* __restrict__ y,
                                               const unsigned int* __restrict__ mask, int n) {
    __shared__ float s_n[32], s_m[32];
    int warp = threadIdx.x >> 5, lane = threadIdx.x & 31;
    int node = blockIdx.x * 32 + warp;
    float nll = 0.f, mm = 0.f;
    if (node < n) {
        float l0 = g_logits[(size_t)node * 64 + lane];
        float l1 = g_logits[(size_t)node * 64 + 32 + lane];
        float mx = fmaxf(l0, l1);
        for (int o = 16; o > 0; o >>= 1) mx = fmaxf(mx, __shfl_xor_sync(0xffffffffu, mx, o));
        float s = expf(l0 - mx) + expf(l1 - mx);
        for (int o = 16; o > 0; o >>= 1) s += __shfl_xor_sync(0xffffffffu, s, o);
        float lse = mx + logf(s);
        int yy = y[node];
        float pick = (yy < 32) ? l0 : l1;
        float ly = __shfl_sync(0xffffffffu, pick, yy & 31);
        mm = (mask[node] != 0u) ? 1.f : 0.f;
        nll = (lse - ly) * mm;
    }
    if (lane == 0) { s_n[warp] = nll; s_m[warp] = mm; }
    __syncthreads();
    if (warp == 0) {
        float a = s_n[lane], b = s_m[lane];
        for (int o = 16; o > 0; o >>= 1) {
            a += __shfl_xor_sync(0xffffffffu, a, o);
            b += __shfl_xor_sync(0xffffffffu, b, o);
        }
        if (lane == 0) { atomicAdd(&g_acc[0], a); atomicAdd(&g_acc[1], b); }
    }
}

__global__ void k_final(float* out) {
    out[0] = g_acc[0] / fmaxf(g_acc[1], 1.0f);
}

// -------- host launch --------
extern "C" void kernel_launch(void* const* d_in, const int* in_sizes, int n_in,
                              void* d_out, int out_size) {
    const float* x    = (const float*)d_in[0];
    const int*   esrc = (const int*)d_in[1];
    const int*   edst = (const int*)d_in[2];
    const int*   y    = (const int*)d_in[3];
    const unsigned int* mask = (const unsigned int*)d_in[4];
    const float* W1l = (const float*)d_in[5];
    const float* b1  = (const float*)d_in[6];
    const float* W1r = (const float*)d_in[7];
    const float* W2l = (const float*)d_in[8];
    const float* b2  = (const float*)d_in[9];
    const float* W2r = (const float*)d_in[10];

    int n = in_sizes[3];   // y: [N]
    int e = in_sizes[1];   // edge_src: [E]

    cudaFuncSetAttribute(k_dense1, cudaFuncAttributeMaxDynamicSharedMemorySize, 192 * 1024);
    cudaFuncSetAttribute(k_dense2, cudaFuncAttributeMaxDynamicSharedMemorySize, 128 * 1024);

    float *pa1, *ph, *pa2, *plog;
    cudaGetSymbolAddress((void**)&pa1,  g_a1);
    cudaGetSymbolAddress((void**)&ph,   g_h);
    cudaGetSymbolAddress((void**)&pa2,  g_a2);
    cudaGetSymbolAddress((void**)&plog, g_logits);

    int nb = (n + 511) / 512;

    k_init<<<(n + 255) / 256, 256>>>(n);
    k_hist<<<(e + 255) / 256, 256>>>(edst, e);
    k_scan1<<<nb, 512>>>(n);
    k_scan2<<<1, 512>>>(nb);
    k_scan3<<<(n + 255) / 256, 256>>>(n);
    k_scatter<<<(e + 255) / 256, 256>>>(esrc, edst, e);

    k_aggr<<<(n + 7) / 8, 256>>>(x, pa1, n);
    k_dense1<<<(n + 63) / 64, 256, 192 * 1024>>>(pa1, x, W1l, W1r, b1, ph, n);
    k_aggr<<<(n + 7) / 8, 256>>>(ph, pa2, n);
    k_dense2<<<(n + 63) / 64, 256, 128 * 1024>>>(pa2, ph, W2l, W2r, b2, plog, n);
    k_loss<<<(n + 31) / 32, 1024>>>(y, mask, n);
    k_final<<<1, 1>>>((float*)d_out);
}

// round 4
// speedup vs baseline: 1.9086x; 1.9086x over previous
#include <cuda_runtime.h>

#define MAXN 65536
#define MAXE 1048576
#define D 128
#define C 64

// -------- scratch (static device globals; no allocation) --------
__device__ __align__(16) float g_a1[(size_t)MAXN * D];
__device__ __align__(16) float g_h [(size_t)MAXN * D];
__device__ __align__(16) float g_u [(size_t)MAXN * D];   // [u_l | u_r] after layer-2 GEMM
__device__ __align__(16) float g_logits[(size_t)MAXN * C];
__device__ int   g_counts[MAXN];
__device__ int   g_offsets[MAXN];
__device__ int   g_scan[MAXN];
__device__ int   g_cursor[MAXN];
__device__ int   g_src_sorted[MAXE];
__device__ int   g_bsum[512];
__device__ float g_acc[2];   // {nll_sum, mask_sum}

__device__ __forceinline__ unsigned f2tf32(float f) {
    unsigned r;
    asm("cvt.rna.tf32.f32 %0, %1;" : "=r"(r) : "f"(f));
    return r;
}

__device__ __forceinline__ void mma_tf32(float c[4], const unsigned a[4], const unsigned b[2]) {
    asm volatile(
        "mma.sync.aligned.m16n8k8.row.col.f32.tf32.tf32.f32 "
        "{%0,%1,%2,%3}, {%4,%5,%6,%7}, {%8,%9}, {%0,%1,%2,%3};"
        : "+f"(c[0]), "+f"(c[1]), "+f"(c[2]), "+f"(c[3])
        : "r"(a[0]), "r"(a[1]), "r"(a[2]), "r"(a[3]), "r"(b[0]), "r"(b[1]));
}

// -------- init --------
__global__ void k_init(int n) {
    int i = blockIdx.x * blockDim.x + threadIdx.x;
    if (i < n) { g_counts[i] = 0; g_cursor[i] = 0; }
    if (i == 0) { g_acc[0] = 0.f; g_acc[1] = 0.f; }
}

// -------- CSR build --------
__global__ void k_hist(const int* __restrict__ dst, int e) {
    int i = blockIdx.x * blockDim.x + threadIdx.x;
    if (i < e) atomicAdd(&g_counts[dst[i]], 1);
}

__global__ void k_scan1(int n) {
    __shared__ int sm[512];
    int i = blockIdx.x * 512 + threadIdx.x;
    int v = (i < n) ? g_counts[i] : 0;
    sm[threadIdx.x] = v; __syncthreads();
    for (int off = 1; off < 512; off <<= 1) {
        int t = (threadIdx.x >= off) ? sm[threadIdx.x - off] : 0;
        __syncthreads();
        sm[threadIdx.x] += t;
        __syncthreads();
    }
    if (i < n) g_scan[i] = sm[threadIdx.x];
    if (threadIdx.x == 511) g_bsum[blockIdx.x] = sm[511];
}

__global__ void k_scan2(int nb) {
    __shared__ int sm[512];
    int i = threadIdx.x;
    int v = (i < nb) ? g_bsum[i] : 0;
    sm[i] = v; __syncthreads();
    for (int off = 1; off < 512; off <<= 1) {
        int t = (i >= off) ? sm[i - off] : 0;
        __syncthreads();
        sm[i] += t;
        __syncthreads();
    }
    if (i < nb) g_bsum[i] = sm[i] - v;   // exclusive prefix of block sums
}

__global__ void k_scan3(int n) {
    int i = blockIdx.x * blockDim.x + threadIdx.x;
    if (i < n) g_offsets[i] = g_scan[i] - g_counts[i] + g_bsum[i >> 9];
}

__global__ void k_scatter(const int* __restrict__ src, const int* __restrict__ dst, int e) {
    int i = blockIdx.x * blockDim.x + threadIdx.x;
    if (i < e) {
        int d = dst[i];
        int p = g_offsets[d] + atomicAdd(&g_cursor[d], 1);
        g_src_sorted[p] = src[i];
    }
}

// -------- mean aggregation: one warp per node, 128-wide --------
__global__ void __launch_bounds__(256) k_aggr(const float* __restrict__ in,
                                              float* __restrict__ out, int n) {
    int w    = (blockIdx.x * blockDim.x + threadIdx.x) >> 5;
    int lane = threadIdx.x & 31;
    if (w >= n) return;
    int start = g_offsets[w];
    int cnt   = g_counts[w];
    const float4* b = (const float4*)in;
    float4 acc = make_float4(0.f, 0.f, 0.f, 0.f);
    int i = 0;
    for (; i + 1 < cnt; i += 2) {
        int s0 = g_src_sorted[start + i];
        int s1 = g_src_sorted[start + i + 1];
        float4 v0 = b[(size_t)s0 * 32 + lane];
        float4 v1 = b[(size_t)s1 * 32 + lane];
        acc.x += v0.x + v1.x; acc.y += v0.y + v1.y;
        acc.z += v0.z + v1.z; acc.w += v0.w + v1.w;
    }
    if (i < cnt) {
        int s = g_src_sorted[start + i];
        float4 v = b[(size_t)s * 32 + lane];
        acc.x += v.x; acc.y += v.y; acc.z += v.z; acc.w += v.w;
    }
    float inv = 1.0f / fmaxf((float)cnt, 1.0f);
    ((float4*)out)[(size_t)w * 32 + lane] =
        make_float4(acc.x * inv, acc.y * inv, acc.z * inv, acc.w * inv);
}

// ======== tf32 tensor-core GEMM, layer 1 ========
// h = relu([A | X] (N x 256) @ [W1l ; W1r] (256 x 128) + b1)
// block tile 128x128, 8 warps (2x4), warp tile 64x32 (4x4 m16n8k8 mmas)
#define SW_STRIDE 136
#define SA_STRIDE 132

__global__ void __launch_bounds__(256) k_gemm1(const float* __restrict__ A,
                                               const float* __restrict__ X,
                                               const float* __restrict__ Wl,
                                               const float* __restrict__ Wr,
                                               const float* __restrict__ bias,
                                               float* __restrict__ out, int n) {
    extern __shared__ unsigned smem[];
    unsigned* sW = smem;                       // 256 x SW_STRIDE
    unsigned* sA = smem + 256 * SW_STRIDE;     // 128 x SA_STRIDE

    int tid = threadIdx.x;
    // preload both weight blocks (tf32-converted)
    for (int i = tid; i < 128 * 128; i += 256) {
        int k = i >> 7, nn = i & 127;
        sW[k * SW_STRIDE + nn]           = f2tf32(Wl[i]);
        sW[(k + 128) * SW_STRIDE + nn]   = f2tf32(Wr[i]);
    }

    int node0 = blockIdx.x * 128;
    int wid = tid >> 5, lane = tid & 31;
    int gid = lane >> 2, tig = lane & 3;
    int wm = wid >> 2, wn = wid & 3;

    float acc[4][4][4];
#pragma unroll
    for (int mi = 0; mi < 4; mi++)
#pragma unroll
        for (int ni = 0; ni < 4; ni++)
#pragma unroll
            for (int r = 0; r < 4; r++) acc[mi][ni][r] = 0.f;

#pragma unroll
    for (int phase = 0; phase < 2; phase++) {
        const float4* src = (const float4*)(phase == 0 ? A : X);
        __syncthreads();   // previous phase's reads done before overwrite
        for (int i = tid; i < 128 * 32; i += 256) {
            int r = i >> 5, c4 = i & 31;
            int node = node0 + r;
            float4 v = make_float4(0.f, 0.f, 0.f, 0.f);
            if (node < n) v = src[(size_t)node * 32 + c4];
            unsigned* p = sA + r * SA_STRIDE + c4 * 4;
            p[0] = f2tf32(v.x); p[1] = f2tf32(v.y);
            p[2] = f2tf32(v.z); p[3] = f2tf32(v.w);
        }
        __syncthreads();

        int kw0 = phase * 128;
#pragma unroll
        for (int k8 = 0; k8 < 16; k8++) {
            int k0 = k8 * 8;
            unsigned afr[4][4];
#pragma unroll
            for (int mi = 0; mi < 4; mi++) {
                int m = wm * 64 + mi * 16;
                afr[mi][0] = sA[(m + gid) * SA_STRIDE + k0 + tig];
                afr[mi][1] = sA[(m + gid + 8) * SA_STRIDE + k0 + tig];
                afr[mi][2] = sA[(m + gid) * SA_STRIDE + k0 + tig + 4];
                afr[mi][3] = sA[(m + gid + 8) * SA_STRIDE + k0 + tig + 4];
            }
            unsigned bfr[4][2];
#pragma unroll
            for (int ni = 0; ni < 4; ni++) {
                int nc = wn * 32 + ni * 8;
                bfr[ni][0] = sW[(kw0 + k0 + tig) * SW_STRIDE + nc + gid];
                bfr[ni][1] = sW[(kw0 + k0 + tig + 4) * SW_STRIDE + nc + gid];
            }
#pragma unroll
            for (int mi = 0; mi < 4; mi++)
#pragma unroll
                for (int ni = 0; ni < 4; ni++)
                    mma_tf32(acc[mi][ni], afr[mi], bfr[ni]);
        }
    }

    // epilogue: bias + relu
#pragma unroll
    for (int mi = 0; mi < 4; mi++) {
#pragma unroll
        for (int ni = 0; ni < 4; ni++) {
            int m = node0 + wm * 64 + mi * 16;
            int col = wn * 32 + ni * 8 + 2 * tig;
            float bv0 = bias[col], bv1 = bias[col + 1];
            int r0 = m + gid, r1 = m + gid + 8;
            if (r0 < n) {
                out[(size_t)r0 * 128 + col]     = fmaxf(acc[mi][ni][0] + bv0, 0.f);
                out[(size_t)r0 * 128 + col + 1] = fmaxf(acc[mi][ni][1] + bv1, 0.f);
            }
            if (r1 < n) {
                out[(size_t)r1 * 128 + col]     = fmaxf(acc[mi][ni][2] + bv0, 0.f);
                out[(size_t)r1 * 128 + col + 1] = fmaxf(acc[mi][ni][3] + bv1, 0.f);
            }
        }
    }
}

// ======== tf32 tensor-core GEMM, layer 2 ========
// u = h (N x 128) @ [W2l | W2r] (128 x 128); no bias, no activation
__global__ void __launch_bounds__(256) k_gemm2(const float* __restrict__ H,
                                               const float* __restrict__ Wl,
                                               const float* __restrict__ Wr,
                                               float* __restrict__ out, int n) {
    extern __shared__ unsigned smem[];
    unsigned* sW = smem;                       // 128 x SW_STRIDE
    unsigned* sA = smem + 128 * SW_STRIDE;     // 128 x SA_STRIDE

    int tid = threadIdx.x;
    for (int i = tid; i < 128 * 64; i += 256) {
        int k = i >> 6, nn = i & 63;
        sW[k * SW_STRIDE + nn]      = f2tf32(Wl[i]);
        sW[k * SW_STRIDE + 64 + nn] = f2tf32(Wr[i]);
    }

    int node0 = blockIdx.x * 128;
    const float4* src = (const float4*)H;
    for (int i = tid; i < 128 * 32; i += 256) {
        int r = i >> 5, c4 = i & 31;
        int node = node0 + r;
        float4 v = make_float4(0.f, 0.f, 0.f, 0.f);
        if (node < n) v = src[(size_t)node * 32 + c4];
        unsigned* p = sA + r * SA_STRIDE + c4 * 4;
        p[0] = f2tf32(v.x); p[1] = f2tf32(v.y);
        p[2] = f2tf32(v.z); p[3] = f2tf32(v.w);
    }
    __syncthreads();

    int wid = tid >> 5, lane = tid & 31;
    int gid = lane >> 2, tig = lane & 3;
    int wm = wid >> 2, wn = wid & 3;

    float acc[4][4][4];
#pragma unroll
    for (int mi = 0; mi < 4; mi++)
#pragma unroll
        for (int ni = 0; ni < 4; ni++)
#pragma unroll
            for (int r = 0; r < 4; r++) acc[mi][ni][r] = 0.f;

#pragma unroll
    for (int k8 = 0; k8 < 16; k8++) {
        int k0 = k8 * 8;
        unsigned afr[4][4];
#pragma unroll
        for (int mi = 0; mi < 4; mi++) {
            int m = wm * 64 + mi * 16;
            afr[mi][0] = sA[(m + gid) * SA_STRIDE + k0 + tig];
            afr[mi][1] = sA[(m + gid + 8) * SA_STRIDE + k0 + tig];
            afr[mi][2] = sA[(m + gid) * SA_STRIDE + k0 + tig + 4];
            afr[mi][3] = sA[(m + gid + 8) * SA_STRIDE + k0 + tig + 4];
        }
        unsigned bfr[4][2];
#pragma unroll
        for (int ni = 0; ni < 4; ni++) {
            int nc = wn * 32 + ni * 8;
            bfr[ni][0] = sW[(k0 + tig) * SW_STRIDE + nc + gid];
            bfr[ni][1] = sW[(k0 + tig + 4) * SW_STRIDE + nc + gid];
        }
#pragma unroll
        for (int mi = 0; mi < 4; mi++)
#pragma unroll
            for (int ni = 0; ni < 4; ni++)
                mma_tf32(acc[mi][ni], afr[mi], bfr[ni]);
    }

#pragma unroll
    for (int mi = 0; mi < 4; mi++) {
#pragma unroll
        for (int ni = 0; ni < 4; ni++) {
            int m = node0 + wm * 64 + mi * 16;
            int col = wn * 32 + ni * 8 + 2 * tig;
            int r0 = m + gid, r1 = m + gid + 8;
            if (r0 < n) {
                out[(size_t)r0 * 128 + col]     = acc[mi][ni][0];
                out[(size_t)r0 * 128 + col + 1] = acc[mi][ni][1];
            }
            if (r1 < n) {
                out[(size_t)r1 * 128 + col]     = acc[mi][ni][2];
                out[(size_t)r1 * 128 + col + 1] = acc[mi][ni][3];
            }
        }
    }
}

// -------- 64-wide aggregation of u_l + fused epilogue: logits = mean + u_r + b2 --------
__global__ void __launch_bounds__(256) k_aggr64(const float* __restrict__ u,
                                                const float* __restrict__ b2,
                                                float* __restrict__ logits, int n) {
    int w    = (blockIdx.x * blockDim.x + threadIdx.x) >> 5;
    int lane = threadIdx.x & 31;
    if (w >= n) return;
    int start = g_offsets[w];
    int cnt   = g_counts[w];
    float2 acc = make_float2(0.f, 0.f);
    int i = 0;
    for (; i + 1 < cnt; i += 2) {
        int s0 = g_src_sorted[start + i];
        int s1 = g_src_sorted[start + i + 1];
        float2 v0 = ((const float2*)(u + (size_t)s0 * 128))[lane];
        float2 v1 = ((const float2*)(u + (size_t)s1 * 128))[lane];
        acc.x += v0.x + v1.x; acc.y += v0.y + v1.y;
    }
    if (i < cnt) {
        int s = g_src_sorted[start + i];
        float2 v = ((const float2*)(u + (size_t)s * 128))[lane];
        acc.x += v.x; acc.y += v.y;
    }
    float inv = 1.0f / fmaxf((float)cnt, 1.0f);
    float2 r  = ((const float2*)(u + (size_t)w * 128 + 64))[lane];
    float2 bb = ((const float2*)b2)[lane];
    ((float2*)(logits + (size_t)w * 64))[lane] =
        make_float2(acc.x * inv + r.x + bb.x, acc.y * inv + r.y + bb.y);
}

// -------- loss: warp-per-node logsumexp + masked NLL reduction --------
__global__ void __launch_bounds__(1024) k_loss(const int* __restrict__ y,
                                               const unsigned int* __restrict__ mask, int n) {
    __shared__ float s_n[32], s_m[32];
    int warp = threadIdx.x >> 5, lane = threadIdx.x & 31;
    int node = blockIdx.x * 32 + warp;
    float nll = 0.f, mm = 0.f;
    if (node < n) {
        float l0 = g_logits[(size_t)node * 64 + lane];
        float l1 = g_logits[(size_t)node * 64 + 32 + lane];
        float mx = fmaxf(l0, l1);
        for (int o = 16; o > 0; o >>= 1) mx = fmaxf(mx, __shfl_xor_sync(0xffffffffu, mx, o));
        float s = expf(l0 - mx) + expf(l1 - mx);
        for (int o = 16; o > 0; o >>= 1) s += __shfl_xor_sync(0xffffffffu, s, o);
        float lse = mx + logf(s);
        int yy = y[node];
        float pick = (yy < 32) ? l0 : l1;
        float ly = __shfl_sync(0xffffffffu, pick, yy & 31);
        mm = (mask[node] != 0u) ? 1.f : 0.f;
        nll = (lse - ly) * mm;
    }
    if (lane == 0) { s_n[warp] = nll; s_m[warp] = mm; }
    __syncthreads();
    if (warp == 0) {
        float a = s_n[lane], b = s_m[lane];
        for (int o = 16; o > 0; o >>= 1) {
            a += __shfl_xor_sync(0xffffffffu, a, o);
            b += __shfl_xor_sync(0xffffffffu, b, o);
        }
        if (lane == 0) { atomicAdd(&g_acc[0], a); atomicAdd(&g_acc[1], b); }
    }
}

__global__ void k_final(float* out) {
    out[0] = g_acc[0] / fmaxf(g_acc[1], 1.0f);
}

// -------- host launch --------
extern "C" void kernel_launch(void* const* d_in, const int* in_sizes, int n_in,
                              void* d_out, int out_size) {
    const float* x    = (const float*)d_in[0];
    const int*   esrc = (const int*)d_in[1];
    const int*   edst = (const int*)d_in[2];
    const int*   y    = (const int*)d_in[3];
    const unsigned int* mask = (const unsigned int*)d_in[4];
    const float* W1l = (const float*)d_in[5];
    const float* b1  = (const float*)d_in[6];
    const float* W1r = (const float*)d_in[7];
    const float* W2l = (const float*)d_in[8];
    const float* b2  = (const float*)d_in[9];
    const float* W2r = (const float*)d_in[10];

    int n = in_sizes[3];   // y: [N]
    int e = in_sizes[1];   // edge_src: [E]

    const int smem1 = (256 * SW_STRIDE + 128 * SA_STRIDE) * 4;  // 206,848 B
    const int smem2 = (128 * SW_STRIDE + 128 * SA_STRIDE) * 4;  // 137,216 B
    cudaFuncSetAttribute(k_gemm1, cudaFuncAttributeMaxDynamicSharedMemorySize, smem1);
    cudaFuncSetAttribute(k_gemm2, cudaFuncAttributeMaxDynamicSharedMemorySize, smem2);

    float *pa1, *ph, *pu, *plog;
    cudaGetSymbolAddress((void**)&pa1,  g_a1);
    cudaGetSymbolAddress((void**)&ph,   g_h);
    cudaGetSymbolAddress((void**)&pu,   g_u);
    cudaGetSymbolAddress((void**)&plog, g_logits);

    int nb = (n + 511) / 512;

    k_init<<<(n + 255) / 256, 256>>>(n);
    k_hist<<<(e + 255) / 256, 256>>>(edst, e);
    k_scan1<<<nb, 512>>>(n);
    k_scan2<<<1, 512>>>(nb);
    k_scan3<<<(n + 255) / 256, 256>>>(n);
    k_scatter<<<(e + 255) / 256, 256>>>(esrc, edst, e);

    k_aggr<<<(n + 7) / 8, 256>>>(x, pa1, n);
    k_gemm1<<<(n + 127) / 128, 256, smem1>>>(pa1, x, W1l, W1r, b1, ph, n);
    k_gemm2<<<(n + 127) / 128, 256, smem2>>>(ph, W2l, W2r, pu, n);
    k_aggr64<<<(n + 7) / 8, 256>>>(pu, b2, plog, n);
    k_loss<<<(n + 31) / 32, 1024>>>(y, mask, n);
    k_final<<<1, 1>>>((float*)d_out);
}

// round 5
// speedup vs baseline: 2.3737x; 1.2437x over previous
#include <cuda_runtime.h>
#include <cuda_bf16.h>

#define MAXN 65536
#define MAXE 1048576
#define D 128
#define C 64

// -------- scratch (static device globals; no allocation) --------
__device__ __align__(16) unsigned g_xb [(size_t)MAXN * 64];  // x, bf16 packed pairs
__device__ __align__(16) unsigned g_a1b[(size_t)MAXN * 64];  // aggr(x), bf16
__device__ __align__(16) unsigned g_hb [(size_t)MAXN * 64];  // h, bf16
__device__ __align__(16) unsigned g_ub [(size_t)MAXN * 32];  // u_l, bf16 (64 wide)
__device__ __align__(16) float    g_ur [(size_t)MAXN * C];   // u_r, fp32
__device__ __align__(16) float    g_logits[(size_t)MAXN * C];
__device__ int   g_counts[MAXN];
__device__ int   g_offsets[MAXN];
__device__ int   g_scan[MAXN];
__device__ int   g_cursor[MAXN];
__device__ int   g_src_sorted[MAXE];
__device__ int   g_bsum[512];
__device__ float g_acc[2];   // {nll_sum, mask_sum}

__device__ __forceinline__ unsigned pack_bf2(float a, float b) {
    __nv_bfloat162 p = __floats2bfloat162_rn(a, b);   // x=a (low), y=b (high)
    return *reinterpret_cast<unsigned*>(&p);
}
__device__ __forceinline__ float2 unpack_bf2(unsigned w) {
    return __bfloat1622float2(*reinterpret_cast<__nv_bfloat162*>(&w));
}

__device__ __forceinline__ void mma_bf16(float c[4], const unsigned a[4], const unsigned b[2]) {
    asm volatile(
        "mma.sync.aligned.m16n8k16.row.col.f32.bf16.bf16.f32 "
        "{%0,%1,%2,%3}, {%4,%5,%6,%7}, {%8,%9}, {%0,%1,%2,%3};"
        : "+f"(c[0]), "+f"(c[1]), "+f"(c[2]), "+f"(c[3])
        : "r"(a[0]), "r"(a[1]), "r"(a[2]), "r"(a[3]), "r"(b[0]), "r"(b[1]));
}

// -------- init --------
__global__ void k_init(int n) {
    int i = blockIdx.x * blockDim.x + threadIdx.x;
    if (i < n) { g_counts[i] = 0; g_cursor[i] = 0; }
    if (i == 0) { g_acc[0] = 0.f; g_acc[1] = 0.f; }
}

// -------- x -> bf16 --------
__global__ void k_x2bf(const float4* __restrict__ x, int nwords4) {
    int i = blockIdx.x * blockDim.x + threadIdx.x;   // one float4 -> 2 packed words
    if (i < nwords4) {
        float4 v = x[i];
        ((uint2*)g_xb)[i] = make_uint2(pack_bf2(v.x, v.y), pack_bf2(v.z, v.w));
    }
}

// -------- CSR build --------
__global__ void k_hist(const int* __restrict__ dst, int e) {
    int i = blockIdx.x * blockDim.x + threadIdx.x;
    if (i < e) atomicAdd(&g_counts[dst[i]], 1);
}

__global__ void k_scan1(int n) {
    __shared__ int sm[512];
    int i = blockIdx.x * 512 + threadIdx.x;
    int v = (i < n) ? g_counts[i] : 0;
    sm[threadIdx.x] = v; __syncthreads();
    for (int off = 1; off < 512; off <<= 1) {
        int t = (threadIdx.x >= off) ? sm[threadIdx.x - off] : 0;
        __syncthreads();
        sm[threadIdx.x] += t;
        __syncthreads();
    }
    if (i < n) g_scan[i] = sm[threadIdx.x];
    if (threadIdx.x == 511) g_bsum[blockIdx.x] = sm[511];
}

__global__ void k_scan2(int nb) {
    __shared__ int sm[512];
    int i = threadIdx.x;
    int v = (i < nb) ? g_bsum[i] : 0;
    sm[i] = v; __syncthreads();
    for (int off = 1; off < 512; off <<= 1) {
        int t = (i >= off) ? sm[i - off] : 0;
        __syncthreads();
        sm[i] += t;
        __syncthreads();
    }
    if (i < nb) g_bsum[i] = sm[i] - v;
}

__global__ void k_scan3(int n) {
    int i = blockIdx.x * blockDim.x + threadIdx.x;
    if (i < n) g_offsets[i] = g_scan[i] - g_counts[i] + g_bsum[i >> 9];
}

__global__ void k_scatter(const int* __restrict__ src, const int* __restrict__ dst, int e) {
    int i = blockIdx.x * blockDim.x + threadIdx.x;
    if (i < e) {
        int d = dst[i];
        int p = g_offsets[d] + atomicAdd(&g_cursor[d], 1);
        g_src_sorted[p] = src[i];
    }
}

// -------- aggregation 1: mean of bf16 x rows -> bf16 out (warp per node) --------
__global__ void __launch_bounds__(256) k_aggr_bf(int n) {
    int w    = (blockIdx.x * blockDim.x + threadIdx.x) >> 5;
    int lane = threadIdx.x & 31;
    if (w >= n) return;
    int start = g_offsets[w];
    int cnt   = g_counts[w];
    float4 acc = make_float4(0.f, 0.f, 0.f, 0.f);
    for (int i = 0; i < cnt; i++) {
        int s = g_src_sorted[start + i];
        uint2 v = ((const uint2*)(g_xb + (size_t)s * 64))[lane];
        float2 f0 = unpack_bf2(v.x), f1 = unpack_bf2(v.y);
        acc.x += f0.x; acc.y += f0.y; acc.z += f1.x; acc.w += f1.y;
    }
    float inv = 1.0f / fmaxf((float)cnt, 1.0f);
    ((uint2*)(g_a1b + (size_t)w * 64))[lane] =
        make_uint2(pack_bf2(acc.x * inv, acc.y * inv), pack_bf2(acc.z * inv, acc.w * inv));
}

// ======== bf16 tensor-core GEMM, layer 1 ========
// h = relu([A | X] (N x 256) @ [W1l ; W1r] (256 x 128) + b1), h written bf16
// block 128x128, 8 warps (2x4), warp tile 64x32, m16n8k16
#define SWS 136   // sW word stride (8*tig+gid -> conflict-free)
#define SAS 68    // sA word stride (4*gid+tig -> conflict-free)

__global__ void __launch_bounds__(256) k_gemm1(const float* __restrict__ Wl,
                                               const float* __restrict__ Wr,
                                               const float* __restrict__ bias,
                                               int n) {
    extern __shared__ unsigned smem[];
    unsigned* sW = smem;                  // 128 word-rows (k2) x SWS
    unsigned* sA = smem + 128 * SWS;      // 128 rows x SAS

    int tid = threadIdx.x;
    // weights: word-row k2 packs k=2*k2, 2*k2+1 for each n. k2<64 -> W1l, else W1r.
    for (int i = tid; i < 128 * 128; i += 256) {
        int k2 = i >> 7, nn = i & 127;
        const float* W = (k2 < 64) ? Wl : Wr;
        int kk = (k2 & 63) * 2;
        sW[k2 * SWS + nn] = pack_bf2(W[kk * 128 + nn], W[(kk + 1) * 128 + nn]);
    }

    int node0 = blockIdx.x * 128;
    int wid = tid >> 5, lane = tid & 31;
    int gid = lane >> 2, tig = lane & 3;
    int wm = wid >> 2, wn = wid & 3;

    float acc[4][4][4];
#pragma unroll
    for (int mi = 0; mi < 4; mi++)
#pragma unroll
        for (int ni = 0; ni < 4; ni++)
#pragma unroll
            for (int r = 0; r < 4; r++) acc[mi][ni][r] = 0.f;

#pragma unroll
    for (int phase = 0; phase < 2; phase++) {
        const uint2* src = (const uint2*)(phase == 0 ? g_a1b : g_xb);
        __syncthreads();
        for (int i = tid; i < 128 * 32; i += 256) {   // uint2 granules
            int r = i >> 5, c2 = i & 31;
            int node = node0 + r;
            uint2 v = make_uint2(0u, 0u);
            if (node < n) v = src[(size_t)node * 32 + c2];
            sA[r * SAS + c2 * 2]     = v.x;
            sA[r * SAS + c2 * 2 + 1] = v.y;
        }
        __syncthreads();

        int kw0 = phase * 64;
#pragma unroll
        for (int s = 0; s < 8; s++) {
            int kw = s * 8;
            unsigned afr[4][4];
#pragma unroll
            for (int mi = 0; mi < 4; mi++) {
                int m = wm * 64 + mi * 16;
                afr[mi][0] = sA[(m + gid) * SAS + kw + tig];
                afr[mi][1] = sA[(m + gid + 8) * SAS + kw + tig];
                afr[mi][2] = sA[(m + gid) * SAS + kw + 4 + tig];
                afr[mi][3] = sA[(m + gid + 8) * SAS + kw + 4 + tig];
            }
            unsigned bfr[4][2];
#pragma unroll
            for (int ni = 0; ni < 4; ni++) {
                int nc = wn * 32 + ni * 8;
                bfr[ni][0] = sW[(kw0 + kw + tig) * SWS + nc + gid];
                bfr[ni][1] = sW[(kw0 + kw + 4 + tig) * SWS + nc + gid];
            }
#pragma unroll
            for (int mi = 0; mi < 4; mi++)
#pragma unroll
                for (int ni = 0; ni < 4; ni++)
                    mma_bf16(acc[mi][ni], afr[mi], bfr[ni]);
        }
    }

    // epilogue: bias + relu -> bf16 packed h
#pragma unroll
    for (int mi = 0; mi < 4; mi++) {
#pragma unroll
        for (int ni = 0; ni < 4; ni++) {
            int m = node0 + wm * 64 + mi * 16;
            int col = wn * 32 + ni * 8 + 2 * tig;
            float bv0 = bias[col], bv1 = bias[col + 1];
            int r0 = m + gid, r1 = m + gid + 8;
            int wrd = col >> 1;
            if (r0 < n)
                g_hb[(size_t)r0 * 64 + wrd] = pack_bf2(fmaxf(acc[mi][ni][0] + bv0, 0.f),
                                                       fmaxf(acc[mi][ni][1] + bv1, 0.f));
            if (r1 < n)
                g_hb[(size_t)r1 * 64 + wrd] = pack_bf2(fmaxf(acc[mi][ni][2] + bv0, 0.f),
                                                       fmaxf(acc[mi][ni][3] + bv1, 0.f));
        }
    }
}

// ======== bf16 GEMM, layer 2: u = h @ [W2l | W2r] (128 x 128) ========
// cols 0..63 (u_l) -> bf16 g_ub; cols 64..127 (u_r) -> fp32 g_ur
__global__ void __launch_bounds__(256) k_gemm2(const float* __restrict__ Wl,
                                               const float* __restrict__ Wr,
                                               int n) {
    extern __shared__ unsigned smem[];
    unsigned* sW = smem;                 // 64 word-rows x SWS
    unsigned* sA = smem + 64 * SWS;      // 128 rows x SAS

    int tid = threadIdx.x;
    for (int i = tid; i < 64 * 128; i += 256) {
        int k2 = i >> 7, nn = i & 127;
        const float* W = (nn < 64) ? Wl : Wr;
        int cc = nn & 63;
        sW[k2 * SWS + nn] = pack_bf2(W[(2 * k2) * 64 + cc], W[(2 * k2 + 1) * 64 + cc]);
    }

    int node0 = blockIdx.x * 128;
    const uint2* src = (const uint2*)g_hb;
    for (int i = tid; i < 128 * 32; i += 256) {
        int r = i >> 5, c2 = i & 31;
        int node = node0 + r;
        uint2 v = make_uint2(0u, 0u);
        if (node < n) v = src[(size_t)node * 32 + c2];
        sA[r * SAS + c2 * 2]     = v.x;
        sA[r * SAS + c2 * 2 + 1] = v.y;
    }
    __syncthreads();

    int wid = tid >> 5, lane = tid & 31;
    int gid = lane >> 2, tig = lane & 3;
    int wm = wid >> 2, wn = wid & 3;

    float acc[4][4][4];
#pragma unroll
    for (int mi = 0; mi < 4; mi++)
#pragma unroll
        for (int ni = 0; ni < 4; ni++)
#pragma unroll
            for (int r = 0; r < 4; r++) acc[mi][ni][r] = 0.f;

#pragma unroll
    for (int s = 0; s < 8; s++) {
        int kw = s * 8;
        unsigned afr[4][4];
#pragma unroll
        for (int mi = 0; mi < 4; mi++) {
            int m = wm * 64 + mi * 16;
            afr[mi][0] = sA[(m + gid) * SAS + kw + tig];
            afr[mi][1] = sA[(m + gid + 8) * SAS + kw + tig];
            afr[mi][2] = sA[(m + gid) * SAS + kw + 4 + tig];
            afr[mi][3] = sA[(m + gid + 8) * SAS + kw + 4 + tig];
        }
        unsigned bfr[4][2];
#pragma unroll
        for (int ni = 0; ni < 4; ni++) {
            int nc = wn * 32 + ni * 8;
            bfr[ni][0] = sW[(kw + tig) * SWS + nc + gid];
            bfr[ni][1] = sW[(kw + 4 + tig) * SWS + nc + gid];
        }
#pragma unroll
        for (int mi = 0; mi < 4; mi++)
#pragma unroll
            for (int ni = 0; ni < 4; ni++)
                mma_bf16(acc[mi][ni], afr[mi], bfr[ni]);
    }

#pragma unroll
    for (int mi = 0; mi < 4; mi++) {
#pragma unroll
        for (int ni = 0; ni < 4; ni++) {
            int m = node0 + wm * 64 + mi * 16;
            int col = wn * 32 + ni * 8 + 2 * tig;
            int r0 = m + gid, r1 = m + gid + 8;
            if (col < 64) {
                int wrd = col >> 1;
                if (r0 < n) g_ub[(size_t)r0 * 32 + wrd] = pack_bf2(acc[mi][ni][0], acc[mi][ni][1]);
                if (r1 < n) g_ub[(size_t)r1 * 32 + wrd] = pack_bf2(acc[mi][ni][2], acc[mi][ni][3]);
            } else {
                int cc = col - 64;
                if (r0 < n) {
                    g_ur[(size_t)r0 * 64 + cc]     = acc[mi][ni][0];
                    g_ur[(size_t)r0 * 64 + cc + 1] = acc[mi][ni][1];
                }
                if (r1 < n) {
                    g_ur[(size_t)r1 * 64 + cc]     = acc[mi][ni][2];
                    g_ur[(size_t)r1 * 64 + cc + 1] = acc[mi][ni][3];
                }
            }
        }
    }
}

// -------- aggregation 2 (64-wide bf16 u_l) + fused epilogue: logits = mean + u_r + b2 --------
__global__ void __launch_bounds__(256) k_aggr64(const float* __restrict__ b2, int n) {
    int w    = (blockIdx.x * blockDim.x + threadIdx.x) >> 5;
    int lane = threadIdx.x & 31;
    if (w >= n) return;
    int start = g_offsets[w];
    int cnt   = g_counts[w];
    float2 acc = make_float2(0.f, 0.f);
    for (int i = 0; i < cnt; i++) {
        int s = g_src_sorted[start + i];
        float2 f = unpack_bf2(g_ub[(size_t)s * 32 + lane]);
        acc.x += f.x; acc.y += f.y;
    }
    float inv = 1.0f / fmaxf((float)cnt, 1.0f);
    float2 r  = ((const float2*)(g_ur + (size_t)w * 64))[lane];
    float2 bb = ((const float2*)b2)[lane];
    ((float2*)(g_logits + (size_t)w * 64))[lane] =
        make_float2(acc.x * inv + r.x + bb.x, acc.y * inv + r.y + bb.y);
}

// -------- loss: warp-per-node logsumexp + masked NLL reduction --------
__global__ void __launch_bounds__(1024) k_loss(const int* __restrict__ y,
                                               const unsigned int* __restrict__ mask, int n) {
    __shared__ float s_n[32], s_m[32];
    int warp = threadIdx.x >> 5, lane = threadIdx.x & 31;
    int node = blockIdx.x * 32 + warp;
    float nll = 0.f, mm = 0.f;
    if (node < n) {
        float l0 = g_logits[(size_t)node * 64 + lane];
        float l1 = g_logits[(size_t)node * 64 + 32 + lane];
        float mx = fmaxf(l0, l1);
        for (int o = 16; o > 0; o >>= 1) mx = fmaxf(mx, __shfl_xor_sync(0xffffffffu, mx, o));
        float s = expf(l0 - mx) + expf(l1 - mx);
        for (int o = 16; o > 0; o >>= 1) s += __shfl_xor_sync(0xffffffffu, s, o);
        float lse = mx + logf(s);
        int yy = y[node];
        float pick = (yy < 32) ? l0 : l1;
        float ly = __shfl_sync(0xffffffffu, pick, yy & 31);
        mm = (mask[node] != 0u) ? 1.f : 0.f;
        nll = (lse - ly) * mm;
    }
    if (lane == 0) { s_n[warp] = nll; s_m[warp] = mm; }
    __syncthreads();
    if (warp == 0) {
        float a = s_n[lane], b = s_m[lane];
        for (int o = 16; o > 0; o >>= 1) {
            a += __shfl_xor_sync(0xffffffffu, a, o);
            b += __shfl_xor_sync(0xffffffffu, b, o);
        }
        if (lane == 0) { atomicAdd(&g_acc[0], a); atomicAdd(&g_acc[1], b); }
    }
}

__global__ void k_final(float* out) {
    out[0] = g_acc[0] / fmaxf(g_acc[1], 1.0f);
}

// -------- host launch --------
extern "C" void kernel_launch(void* const* d_in, const int* in_sizes, int n_in,
                              void* d_out, int out_size) {
    const float* x    = (const float*)d_in[0];
    const int*   esrc = (const int*)d_in[1];
    const int*   edst = (const int*)d_in[2];
    const int*   y    = (const int*)d_in[3];
    const unsigned int* mask = (const unsigned int*)d_in[4];
    const float* W1l = (const float*)d_in[5];
    const float* b1  = (const float*)d_in[6];
    const float* W1r = (const float*)d_in[7];
    const float* W2l = (const float*)d_in[8];
    const float* b2  = (const float*)d_in[9];
    const float* W2r = (const float*)d_in[10];

    int n = in_sizes[3];   // y: [N]
    int e = in_sizes[1];   // edge_src: [E]

    const int smem1 = (128 * SWS + 128 * SAS) * 4;  // 104,448 B
    const int smem2 = (64 * SWS + 128 * SAS) * 4;   //  69,632 B
    cudaFuncSetAttribute(k_gemm1, cudaFuncAttributeMaxDynamicSharedMemorySize, smem1);
    cudaFuncSetAttribute(k_gemm2, cudaFuncAttributeMaxDynamicSharedMemorySize, smem2);

    int nb = (n + 511) / 512;

    k_init<<<(n + 255) / 256, 256>>>(n);
    k_x2bf<<<(n * 32 + 255) / 256, 256>>>((const float4*)x, n * 32);
    k_hist<<<(e + 255) / 256, 256>>>(edst, e);
    k_scan1<<<nb, 512>>>(n);
    k_scan2<<<1, 512>>>(nb);
    k_scan3<<<(n + 255) / 256, 256>>>(n);
    k_scatter<<<(e + 255) / 256, 256>>>(esrc, edst, e);

    k_aggr_bf<<<(n + 7) / 8, 256>>>(n);
    k_gemm1<<<(n + 127) / 128, 256, smem1>>>(W1l, W1r, b1, n);
    k_gemm2<<<(n + 127) / 128, 256, smem2>>>(W2l, W2r, n);
    k_aggr64<<<(n + 7) / 8, 256>>>(b2, n);
    k_loss<<<(n + 31) / 32, 1024>>>(y, mask, n);
    k_final<<<1, 1>>>((float*)d_out);
}